// round 5
// baseline (speedup 1.0000x reference)
#include <cuda_runtime.h>
#include <cuda_fp16.h>
#include <cstdint>

// ---------------------------------------------------------------------------
// GraphConvolutionLayer: out = segment_sum(vals[e] * (x@W)[src[e]] -> dst[e]) + bias
// R5: GEMM moved to tensor pipe (mma.sync m16n8k8 tf32), fragment-major smem
//     staging for conflict-free LDS. fill stays fused. gather unchanged.
// ---------------------------------------------------------------------------

#define IN_F  128
#define OUT_F 64
#define MAX_NODES 100000
#define CAP 128
#define OVF_CAP 65536

__device__ __half g_support[(size_t)MAX_NODES * OUT_F];
__device__ int    g_count[MAX_NODES];
__device__ int2   g_bucket[(size_t)MAX_NODES * CAP];
__device__ int    g_ovf_count;
__device__ int4   g_ovf[OVF_CAP];

#define BM 128       // rows per block
#define BK 32        // k per stage (4 k-blocks of 8)

__device__ __forceinline__ uint32_t f2tf32(float v) {
    uint32_t t;
    asm("cvt.rna.tf32.f32 %0, %1;" : "=r"(t) : "f"(v));
    return t;
}

// ---------------------------------------------------------------------------
// Kernel 1 (fused): blocks [0,nGemm) -> tf32 tensor GEMM tile; rest -> fill
// ---------------------------------------------------------------------------
__global__ __launch_bounds__(256)
void gemm_fill_kernel(const float* __restrict__ A,   // [M,128]
                      const float* __restrict__ W,   // [128,64]
                      __half*      __restrict__ C,   // [M,64] fp16
                      int M, int nGemm,
                      const int*   __restrict__ src,
                      const int*   __restrict__ dst,
                      const float* __restrict__ vals,
                      int nE) {
    if ((int)blockIdx.x >= nGemm) {
        int e = (blockIdx.x - nGemm) * blockDim.x + threadIdx.x;
        if (e >= nE) return;
        int   s = __ldg(&src[e]);
        int   d = __ldg(&dst[e]);
        float v = __ldg(&vals[e]);
        int pos = atomicAdd(&g_count[d], 1);
        if (pos < CAP) {
            g_bucket[(size_t)d * CAP + pos] = make_int2(s, __float_as_int(v));
        } else {
            int o = atomicAdd(&g_ovf_count, 1);
            if (o < OVF_CAP) g_ovf[o] = make_int4(s, d, __float_as_int(v), 0);
        }
        return;
    }

    // ---------------- tf32 tensor-core GEMM ----------------
    // Fragment-major smem: conflict-free LDS.128 (A) / LDS.64 (B).
    // As[g][kb][lane][comp]: g = 16-row group (0..7), kb = k-block of 8 (0..3)
    //   comp: a0=(r,c) a1=(r+8,c) a2=(r,c+4) a3=(r+8,c+4), r=lane>>2, c=lane&3
    // Bs[nb][kb][lane][comp]: nb = 8-col group (0..7)
    //   comp: b0=(k=lane&3, n=lane>>2) b1=(k+4, n)
    __shared__ uint32_t As[8 * 4 * 32 * 4];   // 16 KB
    __shared__ uint32_t Bs[8 * 4 * 32 * 2];   //  8 KB

    int tid  = threadIdx.x;
    int lane = tid & 31;
    int wid  = tid >> 5;          // 0..7
    int wm   = wid >> 1;          // 0..3  (M: 32 rows each)
    int wn   = wid & 1;           // 0..1  (N: 32 cols each)
    int rowBase = blockIdx.x * BM;

    float acc[2][4][4];
    #pragma unroll
    for (int i = 0; i < 2; i++)
        #pragma unroll
        for (int j = 0; j < 4; j++)
            #pragma unroll
            for (int q = 0; q < 4; q++) acc[i][j][q] = 0.f;

    for (int kBase = 0; kBase < IN_F; kBase += BK) {
        // --- stage A tile (128 x 32): 1024 float4, 4 per thread ---
        #pragma unroll
        for (int it = 0; it < 4; it++) {
            int idx = tid + it * 256;         // 0..1023
            int row = idx >> 3;               // 0..127
            int c4  = idx & 7;                // which float4 in the 32-k slice
            int grow = rowBase + row;
            float4 v = make_float4(0.f, 0.f, 0.f, 0.f);
            if (grow < M)
                v = *reinterpret_cast<const float4*>(A + (size_t)grow * IN_F + kBase + c4 * 4);
            int g   = row >> 4;
            int rr  = row & 15;
            int sel = rr >> 3;                // 0: comps {0,2}, 1: comps {1,3}
            int lr  = rr & 7;
            int kb  = c4 >> 1;
            int hi  = c4 & 1;                 // 0: c in [0,4), 1: c in [4,8)
            // element e -> lane lr*4+e, comp hi*2+sel
            int base = (((g * 4 + kb) * 32 + lr * 4) << 2) + hi * 2 + sel;
            As[base +  0] = f2tf32(v.x);
            As[base +  4] = f2tf32(v.y);
            As[base +  8] = f2tf32(v.z);
            As[base + 12] = f2tf32(v.w);
        }
        // --- stage B tile (32 x 64): 512 float4, 2 per thread ---
        #pragma unroll
        for (int it = 0; it < 2; it++) {
            int idx  = tid + it * 256;        // 0..511
            int krow = idx >> 4;              // 0..31
            int n4   = idx & 15;
            float4 v = *reinterpret_cast<const float4*>(W + (size_t)(kBase + krow) * OUT_F + n4 * 4);
            int kb = krow >> 3;
            int w8 = krow & 7;
            int lc = w8 & 3;
            int hi = w8 >> 2;                 // comp
            int nb = n4 >> 1;
            int lgb = (n4 & 1) * 4;           // n within group of 8, base
            // element e -> lane (lgb+e)*4 + lc
            int base = (((nb * 4 + kb) * 32 + lgb * 4 + lc) << 1) + hi;
            Bs[base +  0] = f2tf32(v.x);
            Bs[base +  8] = f2tf32(v.y);
            Bs[base + 16] = f2tf32(v.z);
            Bs[base + 24] = f2tf32(v.w);
        }
        __syncthreads();

        #pragma unroll
        for (int kb = 0; kb < 4; kb++) {
            uint4 fa[2];
            uint2 fb[4];
            #pragma unroll
            for (int i = 0; i < 2; i++)
                fa[i] = *reinterpret_cast<const uint4*>(
                    &As[(((2 * wm + i) * 4 + kb) * 32 + lane) << 2]);
            #pragma unroll
            for (int j = 0; j < 4; j++)
                fb[j] = *reinterpret_cast<const uint2*>(
                    &Bs[(((wn * 4 + j) * 4 + kb) * 32 + lane) << 1]);
            #pragma unroll
            for (int i = 0; i < 2; i++)
                #pragma unroll
                for (int j = 0; j < 4; j++) {
                    asm volatile(
                        "mma.sync.aligned.m16n8k8.row.col.f32.tf32.tf32.f32 "
                        "{%0,%1,%2,%3}, {%4,%5,%6,%7}, {%8,%9}, {%0,%1,%2,%3};"
                        : "+f"(acc[i][j][0]), "+f"(acc[i][j][1]),
                          "+f"(acc[i][j][2]), "+f"(acc[i][j][3])
                        : "r"(fa[i].x), "r"(fa[i].y), "r"(fa[i].z), "r"(fa[i].w),
                          "r"(fb[j].x), "r"(fb[j].y));
                }
        }
        __syncthreads();
    }

    // --- epilogue: fp16 store ---
    #pragma unroll
    for (int i = 0; i < 2; i++) {
        int r0 = rowBase + wm * 32 + i * 16 + (lane >> 2);
        int r1 = r0 + 8;
        #pragma unroll
        for (int j = 0; j < 4; j++) {
            int cbase = wn * 32 + j * 8 + (lane & 3) * 2;
            if (r0 < M) {
                __half2 h = __float22half2_rn(make_float2(acc[i][j][0], acc[i][j][1]));
                *reinterpret_cast<uint32_t*>(C + (size_t)r0 * OUT_F + cbase) = *(uint32_t*)&h;
            }
            if (r1 < M) {
                __half2 h = __float22half2_rn(make_float2(acc[i][j][2], acc[i][j][3]));
                *reinterpret_cast<uint32_t*>(C + (size_t)r1 * OUT_F + cbase) = *(uint32_t*)&h;
            }
        }
    }
}

// ---------------------------------------------------------------------------
// Kernel 2: gather — one warp per dst node (unchanged)
// ---------------------------------------------------------------------------
__global__ __launch_bounds__(256)
void gather_kernel(const __half* __restrict__ support,
                   const float*  __restrict__ bias,
                   float* __restrict__ out, int M) {
    int w    = (blockIdx.x * blockDim.x + threadIdx.x) >> 5;
    int lane = threadIdx.x & 31;
    if (w >= M) return;

    int deg = g_count[w];
    if (deg > CAP) deg = CAP;

    float2 acc = make_float2(0.f, 0.f);
    const int2* bkt = g_bucket + (size_t)w * CAP;

    #pragma unroll 4
    for (int j = 0; j < deg; j++) {
        int2 pr = __ldg(&bkt[j]);
        float v = __int_as_float(pr.y);
        const uint32_t* row = reinterpret_cast<const uint32_t*>(
            support + (size_t)pr.x * OUT_F);
        uint32_t h2raw = __ldg(&row[lane]);
        float2 f = __half22float2(*reinterpret_cast<__half2*>(&h2raw));
        acc.x += v * f.x;
        acc.y += v * f.y;
    }

    float2 b = __ldg(reinterpret_cast<const float2*>(bias) + lane);
    float2 r = make_float2(acc.x + b.x, acc.y + b.y);
    *reinterpret_cast<float2*>(out + (size_t)w * OUT_F + 2 * lane) = r;
}

// ---------------------------------------------------------------------------
// Kernel 3: overflow backstop (correctness guarantee; no-op in practice)
// ---------------------------------------------------------------------------
__global__ void ovf_kernel(const __half* __restrict__ support,
                           float* __restrict__ out) {
    int n = g_ovf_count;
    if (n > OVF_CAP) n = OVF_CAP;
    if (n <= 0) return;
    int total = n * 16;
    for (int t = blockIdx.x * blockDim.x + threadIdx.x; t < total;
         t += gridDim.x * blockDim.x) {
        int e = t >> 4;
        int j = (t & 15) << 2;
        int4 r = g_ovf[e];
        float v = __int_as_float(r.z);
        const uint32_t* row = reinterpret_cast<const uint32_t*>(
            g_support + (size_t)r.x * OUT_F);
        uint32_t a = __ldg(&row[j >> 1]);
        uint32_t c = __ldg(&row[(j >> 1) + 1]);
        float2 f01 = __half22float2(*reinterpret_cast<__half2*>(&a));
        float2 f23 = __half22float2(*reinterpret_cast<__half2*>(&c));
        float* p = out + (size_t)r.y * OUT_F + j;
        asm volatile("red.global.add.v4.f32 [%0], {%1,%2,%3,%4};"
                     :: "l"(p), "f"(f01.x * v), "f"(f01.y * v),
                        "f"(f23.x * v), "f"(f23.y * v)
                     : "memory");
    }
}

// ---------------------------------------------------------------------------
extern "C" void kernel_launch(void* const* d_in, const int* in_sizes, int n_in,
                              void* d_out, int out_size) {
    const float* x        = (const float*)d_in[0];
    const float* weight   = (const float*)d_in[1];
    const float* bias     = (const float*)d_in[2];
    const int*   edge_src = (const int*)  d_in[3];
    const int*   edge_dst = (const int*)  d_in[4];
    const float* edge_val = (const float*)d_in[5];
    float* out = (float*)d_out;

    int M  = in_sizes[0] / IN_F;
    int nE = in_sizes[3];

    __half* support; cudaGetSymbolAddress((void**)&support, g_support);
    int*    countp;  cudaGetSymbolAddress((void**)&countp, g_count);
    int*    ovfcp;   cudaGetSymbolAddress((void**)&ovfcp, g_ovf_count);

    cudaMemsetAsync(countp, 0, (size_t)M * sizeof(int));
    cudaMemsetAsync(ovfcp, 0, sizeof(int));

    int nGemm = (M + BM - 1) / BM;
    int nFill = (nE + 255) / 256;
    gemm_fill_kernel<<<nGemm + nFill, 256>>>(x, weight, support, M, nGemm,
                                             edge_src, edge_dst, edge_val, nE);

    gather_kernel<<<(M * 32 + 255) / 256, 256>>>(support, bias, out, M);

    ovf_kernel<<<64, 256>>>(support, out);
}